// round 11
// baseline (speedup 1.0000x reference)
#include <cuda_runtime.h>
#include <cuda_bf16.h>
#include <math.h>
#include <stdint.h>

// AFT-full via separable exponent, single persistent kernel, 3 phases:
//   P0 split:  xh/xl, Wh/Wl (qkv concat), Ph/Pl = split(exp(pos))
//   P1 proj:   qkv = x@W^T+b (mma.sync bf16 3-pass); epilogue emits g_q and
//              transposed bf16-split Zt directly
//   P2 aft:    O2 = P @ Z (mma.sync, 3-deep cp.async ring), out=q*num/den
// Phases separated by a sense-reversing software grid barrier (128 CTAs,
// all wave-1 resident on 148 SMs).

#define BSZ   4
#define SEQ   512
#define DIM   128
#define NROW  (BSZ * SEQ)
#define ZN    256
#define NCTA  128

typedef unsigned long long ull;

__device__ __align__(16) float         g_q  [NROW * DIM];
__device__ __align__(16) __nv_bfloat16 g_xh [NROW * DIM];
__device__ __align__(16) __nv_bfloat16 g_xl [NROW * DIM];
__device__ __align__(16) __nv_bfloat16 g_Wh [384 * DIM];
__device__ __align__(16) __nv_bfloat16 g_Wl [384 * DIM];
__device__ __align__(16) __nv_bfloat16 g_Ph [SEQ * SEQ];
__device__ __align__(16) __nv_bfloat16 g_Pl [SEQ * SEQ];
__device__ __align__(16) __nv_bfloat16 g_Zth[BSZ * ZN * SEQ];
__device__ __align__(16) __nv_bfloat16 g_Ztl[BSZ * ZN * SEQ];

__device__ unsigned g_cnt = 0;
__device__ volatile unsigned g_gen = 0;

// ---------------- portable PTX helpers (sm_80+ features only) --------------
__device__ __forceinline__ uint32_t smem_u32(const void* p) {
    uint32_t a;
    asm("{ .reg .u64 t; cvta.to.shared.u64 t, %1; cvt.u32.u64 %0, t; }" : "=r"(a) : "l"(p));
    return a;
}
#define SWZ64(x) ((x) ^ (((x) >> 3) & 0x30))

__device__ __forceinline__ void ldsm4(uint32_t* r, uint32_t addr) {
    asm volatile("ldmatrix.sync.aligned.m8n8.x4.shared.b16 {%0,%1,%2,%3}, [%4];"
        : "=r"(r[0]), "=r"(r[1]), "=r"(r[2]), "=r"(r[3]) : "r"(addr));
}
__device__ __forceinline__ void ldsm2(uint32_t* r, uint32_t addr) {
    asm volatile("ldmatrix.sync.aligned.m8n8.x2.shared.b16 {%0,%1}, [%2];"
        : "=r"(r[0]), "=r"(r[1]) : "r"(addr));
}
__device__ __forceinline__ void mma16816(float* c, const uint32_t* a, const uint32_t* b) {
    asm volatile("mma.sync.aligned.m16n8k16.row.col.f32.bf16.bf16.f32 "
        "{%0,%1,%2,%3}, {%4,%5,%6,%7}, {%8,%9}, {%0,%1,%2,%3};"
        : "+f"(c[0]), "+f"(c[1]), "+f"(c[2]), "+f"(c[3])
        : "r"(a[0]), "r"(a[1]), "r"(a[2]), "r"(a[3]), "r"(b[0]), "r"(b[1]));
}
__device__ __forceinline__ void cpa16(uint32_t s, const void* g) {
    asm volatile("cp.async.ca.shared.global [%0], [%1], 16;" :: "r"(s), "l"(g) : "memory");
}

__device__ __forceinline__ void split_store(__nv_bfloat16* H, __nv_bfloat16* L,
                                            size_t e, float4 v) {
    float a0 = v.x, a1 = v.y, a2 = v.z, a3 = v.w;
    __nv_bfloat16 h0 = __float2bfloat16(a0), h1 = __float2bfloat16(a1);
    __nv_bfloat16 h2 = __float2bfloat16(a2), h3 = __float2bfloat16(a3);
    __nv_bfloat16 l0 = __float2bfloat16(a0 - __bfloat162float(h0));
    __nv_bfloat16 l1 = __float2bfloat16(a1 - __bfloat162float(h1));
    __nv_bfloat16 l2 = __float2bfloat16(a2 - __bfloat162float(h2));
    __nv_bfloat16 l3 = __float2bfloat16(a3 - __bfloat162float(h3));
    *(__nv_bfloat162*)&H[e]     = __nv_bfloat162(h0, h1);
    *(__nv_bfloat162*)&H[e + 2] = __nv_bfloat162(h2, h3);
    *(__nv_bfloat162*)&L[e]     = __nv_bfloat162(l0, l1);
    *(__nv_bfloat162*)&L[e + 2] = __nv_bfloat162(l2, l3);
}

// sense-reversing grid barrier; valid because all NCTA CTAs are resident
__device__ __forceinline__ void gbar() {
    __syncthreads();
    if (threadIdx.x == 0) {
        __threadfence();
        unsigned my = g_gen;
        if (atomicAdd(&g_cnt, 1u) == NCTA - 1) {
            g_cnt = 0;
            __threadfence();
            g_gen = my + 1;
        } else {
            while (g_gen == my) { }
        }
    }
    __syncthreads();
    __threadfence();
}

// ---------------------------------------------------------------------------
__global__ __launch_bounds__(256, 1)
void aft_fused(const float* __restrict__ x,
               const float* __restrict__ Wq, const float* __restrict__ bq,
               const float* __restrict__ Wk, const float* __restrict__ bk,
               const float* __restrict__ Wv, const float* __restrict__ bv,
               const float* __restrict__ pos,
               float* __restrict__ out)
{
    __shared__ __align__(128) char arena[49152];

    const int bid = blockIdx.x;
    const int tid = threadIdx.x;
    const int wid = tid >> 5, lane = tid & 31;
    const int mw  = wid >> 2, nw = wid & 3;

    const int am  = (lane & 7) + ((lane >> 3) & 1) * 8;
    const int akb = (lane >> 4) * 8;
    const int bn  = (lane & 7) + ((lane >> 4) & 1) * 8;
    const int bkb = ((lane >> 3) & 1) * 8;

    // ======================== Phase 0: splits ==============================
    {
        const int gid = bid * 256 + tid;
        #pragma unroll
        for (int it = 0; it < 5; it++) {
            int idx = gid + it * (NCTA * 256);
            if (idx < 65536) {                      // x
                float4 v = ((const float4*)x)[idx];
                split_store(g_xh, g_xl, (size_t)idx * 4, v);
            } else if (idx < 131072) {              // exp(pos)
                int i = idx - 65536;
                float4 p = ((const float4*)pos)[i];
                float4 e;
                e.x = __expf(p.x); e.y = __expf(p.y);
                e.z = __expf(p.z); e.w = __expf(p.w);
                split_store(g_Ph, g_Pl, (size_t)i * 4, e);
            } else if (idx < 143360) {              // W concat
                int i = idx - 131072;
                int e = i * 4;
                int mat = e >> 14;
                int off = e & 16383;
                const float* W = (mat == 0) ? Wq : (mat == 1) ? Wk : Wv;
                float4 v = *(const float4*)&W[off];
                split_store(g_Wh, g_Wl, (size_t)e, v);
            }
        }
    }
    gbar();

    // ======================== Phase 1: projection ==========================
    {
        const int d0 = (bid & 3) * 32;
        const int m0 = (bid >> 2) * 64;

        const uint32_t sm0 = smem_u32(arena);
        const uint32_t sm1 = sm0 + 20480;

        float c[2][3][4] = {};

        auto load_stage = [&](int s) {
            const uint32_t sb = (s & 1) ? sm1 : sm0;
            const int k0 = s * 32;
            #pragma unroll
            for (int i = 0; i < 5; i++) {
                int cch = tid + i * 256;
                const __nv_bfloat16* src;
                uint32_t so; size_t go;
                if (cch < 512) {
                    int hl = cch >> 8, cc = cch & 255;
                    int row = cc >> 2, c16 = cc & 3;
                    so = sb + hl * 4096 + SWZ64(row * 64 + c16 * 16);
                    src = hl ? g_xl : g_xh;
                    go = (size_t)(m0 + row) * 128 + k0 + c16 * 8;
                } else {
                    int v2 = cch - 512;
                    int hl = v2 >= 384, cc = hl ? v2 - 384 : v2;
                    int row = cc >> 2, c16 = cc & 3;
                    so = sb + 8192 + hl * 6144 + SWZ64(row * 64 + c16 * 16);
                    src = hl ? g_Wl : g_Wh;
                    go = (size_t)((row >> 5) * 128 + d0 + (row & 31)) * 128 + k0 + c16 * 8;
                }
                cpa16(so, src + go);
            }
            asm volatile("cp.async.commit_group;" ::: "memory");
        };

        load_stage(0);

        for (int s = 0; s < 4; s++) {
            asm volatile("cp.async.wait_group 0;" ::: "memory");
            __syncthreads();
            if (s < 3) load_stage(s + 1);
            const uint32_t sb = (s & 1) ? sm1 : sm0;
            #pragma unroll
            for (int kk = 0; kk < 2; kk++) {
                uint32_t ah[2][4], al[2][4], bh[6], bl[6];
                #pragma unroll
                for (int ms = 0; ms < 2; ms++) {
                    int rowA = mw * 32 + ms * 16 + am;
                    uint32_t off = SWZ64(rowA * 64 + kk * 32 + akb * 2);
                    ldsm4(ah[ms], sb + off);
                    ldsm4(al[ms], sb + 4096 + off);
                }
                {
                    int rowB = nw * 24 + bn;
                    uint32_t off4 = SWZ64(rowB * 64 + kk * 32 + bkb * 2);
                    ldsm4(bh, sb + 8192 + off4);
                    ldsm4(bl, sb + 14336 + off4);
                    int rowB2 = nw * 24 + 16 + (lane & 7);
                    uint32_t off2 = SWZ64(rowB2 * 64 + kk * 32 + ((lane >> 3) & 1) * 16);
                    ldsm2(bh + 4, sb + 8192 + off2);
                    ldsm2(bl + 4, sb + 14336 + off2);
                }
                #pragma unroll
                for (int ms = 0; ms < 2; ms++)
                    #pragma unroll
                    for (int nf = 0; nf < 3; nf++) {
                        mma16816(c[ms][nf], ah[ms], bh + 2 * nf);
                        mma16816(c[ms][nf], ah[ms], bl + 2 * nf);
                        mma16816(c[ms][nf], al[ms], bh + 2 * nf);
                    }
            }
            __syncthreads();
        }

        // epilogue: E/V exchange in arena, then transposed split write
        float (*Ebuf)[33] = (float(*)[33])arena;
        float (*Vbuf)[33] = (float(*)[33])(arena + 8448);

        #pragma unroll
        for (int ms = 0; ms < 2; ms++)
            #pragma unroll
            for (int nf = 0; nf < 3; nf++) {
                int ncl = nw * 24 + nf * 8;
                int region = ncl >> 5;
                int dcol = (ncl & 31) + 2 * (lane & 3);
                int r0 = mw * 32 + ms * 16 + (lane >> 2);
                #pragma unroll
                for (int h = 0; h < 2; h++) {
                    int r = r0 + 8 * h;
                    float v0 = c[ms][nf][2 * h], v1 = c[ms][nf][2 * h + 1];
                    int d = d0 + dcol;
                    if (region == 0) {
                        float s0 = 1.0f / (1.0f + __expf(-(v0 + bq[d])));
                        float s1 = 1.0f / (1.0f + __expf(-(v1 + bq[d + 1])));
                        *(float2*)&g_q[(size_t)(m0 + r) * 128 + d] = make_float2(s0, s1);
                    } else if (region == 1) {
                        Ebuf[r][dcol]     = __expf(v0 + bk[d]);
                        Ebuf[r][dcol + 1] = __expf(v1 + bk[d + 1]);
                    } else {
                        Vbuf[r][dcol]     = v0 + bv[d];
                        Vbuf[r][dcol + 1] = v1 + bv[d + 1];
                    }
                }
            }
        __syncthreads();

        {
            const int b  = m0 >> 9;
            const int j0 = m0 & 511;
            const int d  = tid >> 3;
            const int jl = (tid & 7) * 8;
            __nv_bfloat16 nh[8], nl[8], dh[8], dl[8];
            #pragma unroll
            for (int i = 0; i < 8; i++) {
                float e = Ebuf[jl + i][d];
                float v = Vbuf[jl + i][d];
                float nm = e * v;
                nh[i] = __float2bfloat16(nm);
                nl[i] = __float2bfloat16(nm - __bfloat162float(nh[i]));
                dh[i] = __float2bfloat16(e);
                dl[i] = __float2bfloat16(e - __bfloat162float(dh[i]));
            }
            size_t rn = (size_t)(b * ZN + d0 + d) * SEQ + j0 + jl;
            size_t rd = (size_t)(b * ZN + 128 + d0 + d) * SEQ + j0 + jl;
            *(uint4*)&g_Zth[rn] = *(const uint4*)nh;
            *(uint4*)&g_Ztl[rn] = *(const uint4*)nl;
            *(uint4*)&g_Zth[rd] = *(const uint4*)dh;
            *(uint4*)&g_Ztl[rd] = *(const uint4*)dl;
        }
    }
    gbar();

    // ======================== Phase 2: AFT GEMM ============================
    {
        const int d0 = (bid & 3) * 32;
        const int m0 = ((bid >> 2) & 7) * 64;
        const int b  = bid >> 5;

        const uint32_t sbase = smem_u32(arena);

        float c[2][2][4] = {};

        auto load_stage = [&](int s) {
            const uint32_t sb = sbase + (uint32_t)(s % 3) * 16384;
            const int k0 = s * 32;
            #pragma unroll
            for (int i = 0; i < 4; i++) {
                int cch  = tid + i * 256;
                int tile = cch >> 8;
                int cc   = cch & 255;
                int row  = cc >> 2, c16 = cc & 3;
                uint32_t so = sb + tile * 4096 + SWZ64(row * 64 + c16 * 16);
                const __nv_bfloat16* src;
                int grow;
                if (tile < 2) {
                    grow = m0 + row;
                    src = (tile == 0) ? g_Ph : g_Pl;
                } else {
                    int rowZ = (row < 32) ? d0 + row : 96 + d0 + row;
                    grow = b * ZN + rowZ;
                    src = (tile == 2) ? g_Zth : g_Ztl;
                }
                cpa16(so, src + (size_t)grow * SEQ + k0 + c16 * 8);
            }
            asm volatile("cp.async.commit_group;" ::: "memory");
        };

        load_stage(0);
        load_stage(1);

        for (int s = 0; s < 16; s++) {
            asm volatile("cp.async.wait_group 1;" ::: "memory");
            __syncthreads();
            if (s < 14) load_stage(s + 2);
            const uint32_t sb = sbase + (uint32_t)(s % 3) * 16384;
            #pragma unroll
            for (int kk = 0; kk < 2; kk++) {
                uint32_t ah[2][4], al[2][4], bh[4], bl[4];
                #pragma unroll
                for (int ms = 0; ms < 2; ms++) {
                    int rowA = mw * 32 + ms * 16 + am;
                    uint32_t off = SWZ64(rowA * 64 + kk * 32 + akb * 2);
                    ldsm4(ah[ms], sb + off);
                    ldsm4(al[ms], sb + 4096 + off);
                }
                {
                    int rowB = nw * 16 + bn;
                    uint32_t off = SWZ64(rowB * 64 + kk * 32 + bkb * 2);
                    ldsm4(bh, sb + 8192 + off);
                    ldsm4(bl, sb + 12288 + off);
                }
                #pragma unroll
                for (int ms = 0; ms < 2; ms++)
                    #pragma unroll
                    for (int ns = 0; ns < 2; ns++) {
                        mma16816(c[ms][ns], ah[ms], bh + 2 * ns);
                        mma16816(c[ms][ns], ah[ms], bl + 2 * ns);
                        mma16816(c[ms][ns], al[ms], bh + 2 * ns);
                    }
            }
        }
        __syncthreads();

        float (*den)[34] = (float(*)[34])(arena + 16384);

        if (nw >= 2) {
            #pragma unroll
            for (int ms = 0; ms < 2; ms++)
                #pragma unroll
                for (int ns = 0; ns < 2; ns++) {
                    int dr = (nw - 2) * 16 + ns * 8 + 2 * (lane & 3);
                    int r  = mw * 32 + ms * 16 + (lane >> 2);
                    *(float2*)&den[r][dr]     = make_float2(c[ms][ns][0], c[ms][ns][1]);
                    *(float2*)&den[r + 8][dr] = make_float2(c[ms][ns][2], c[ms][ns][3]);
                }
        }
        __syncthreads();
        if (nw < 2) {
            #pragma unroll
            for (int ms = 0; ms < 2; ms++)
                #pragma unroll
                for (int ns = 0; ns < 2; ns++) {
                    int dr = nw * 16 + ns * 8 + 2 * (lane & 3);
                    int r  = mw * 32 + ms * 16 + (lane >> 2);
                    #pragma unroll
                    for (int h = 0; h < 2; h++) {
                        int rr   = r + h * 8;
                        int grow = b * SEQ + m0 + rr;
                        float2 dn = *(float2*)&den[rr][dr];
                        float2 q  = *(const float2*)&g_q[(size_t)grow * DIM + d0 + dr];
                        float2 o;
                        o.x = q.x * c[ms][ns][2 * h]     / dn.x;
                        o.y = q.y * c[ms][ns][2 * h + 1] / dn.y;
                        *(float2*)&out[(size_t)grow * DIM + d0 + dr] = o;
                    }
                }
        }
    }
}

// ---------------------------------------------------------------------------
extern "C" void kernel_launch(void* const* d_in, const int* in_sizes, int n_in,
                              void* d_out, int out_size)
{
    const float* x   = (const float*)d_in[0];
    const float* Wq  = (const float*)d_in[1];
    const float* bq  = (const float*)d_in[2];
    const float* Wk  = (const float*)d_in[3];
    const float* bk  = (const float*)d_in[4];
    const float* Wv  = (const float*)d_in[5];
    const float* bv  = (const float*)d_in[6];
    const float* pos = (const float*)d_in[7];
    float* out = (float*)d_out;

    aft_fused<<<NCTA, 256>>>(x, Wq, bq, Wk, bk, Wv, bv, pos, out);
}

// round 12
// speedup vs baseline: 1.0419x; 1.0419x over previous
#include <cuda_runtime.h>
#include <cuda_bf16.h>
#include <math.h>
#include <stdint.h>

// AFT-full via separable exponent, all GEMMs on tensor cores (mma.sync bf16,
// 3-pass Markidis split):
//   L1 split_inputs: xh/xl, Wh/Wl (qkv concat), Ph/Pl = split(exp(pos))
//   L2 proj_mma:     qkv = x@W^T+b; epilogue emits g_q and transposed
//                    bf16-split Zt directly
//   L3 aft_mma:      O2 = P @ Z, 512 threads, split-K over 2 warpgroups,
//                    ratio q*num/den fused in epilogue

#define BSZ   4
#define SEQ   512
#define DIM   128
#define NROW  (BSZ * SEQ)
#define ZN    256

typedef unsigned long long ull;

__device__ __align__(16) float         g_q  [NROW * DIM];
__device__ __align__(16) __nv_bfloat16 g_xh [NROW * DIM];
__device__ __align__(16) __nv_bfloat16 g_xl [NROW * DIM];
__device__ __align__(16) __nv_bfloat16 g_Wh [384 * DIM];
__device__ __align__(16) __nv_bfloat16 g_Wl [384 * DIM];
__device__ __align__(16) __nv_bfloat16 g_Ph [SEQ * SEQ];
__device__ __align__(16) __nv_bfloat16 g_Pl [SEQ * SEQ];
__device__ __align__(16) __nv_bfloat16 g_Zth[BSZ * ZN * SEQ];
__device__ __align__(16) __nv_bfloat16 g_Ztl[BSZ * ZN * SEQ];

// ---------------- portable PTX helpers (sm_80+ features only) --------------
__device__ __forceinline__ uint32_t smem_u32(const void* p) {
    uint32_t a;
    asm("{ .reg .u64 t; cvta.to.shared.u64 t, %1; cvt.u32.u64 %0, t; }" : "=r"(a) : "l"(p));
    return a;
}
#define SWZ64(x) ((x) ^ (((x) >> 3) & 0x30))

__device__ __forceinline__ void ldsm4(uint32_t* r, uint32_t addr) {
    asm volatile("ldmatrix.sync.aligned.m8n8.x4.shared.b16 {%0,%1,%2,%3}, [%4];"
        : "=r"(r[0]), "=r"(r[1]), "=r"(r[2]), "=r"(r[3]) : "r"(addr));
}
__device__ __forceinline__ void ldsm2(uint32_t* r, uint32_t addr) {
    asm volatile("ldmatrix.sync.aligned.m8n8.x2.shared.b16 {%0,%1}, [%2];"
        : "=r"(r[0]), "=r"(r[1]) : "r"(addr));
}
__device__ __forceinline__ void mma16816(float* c, const uint32_t* a, const uint32_t* b) {
    asm volatile("mma.sync.aligned.m16n8k16.row.col.f32.bf16.bf16.f32 "
        "{%0,%1,%2,%3}, {%4,%5,%6,%7}, {%8,%9}, {%0,%1,%2,%3};"
        : "+f"(c[0]), "+f"(c[1]), "+f"(c[2]), "+f"(c[3])
        : "r"(a[0]), "r"(a[1]), "r"(a[2]), "r"(a[3]), "r"(b[0]), "r"(b[1]));
}
__device__ __forceinline__ void cpa16(uint32_t s, const void* g) {
    asm volatile("cp.async.ca.shared.global [%0], [%1], 16;" :: "r"(s), "l"(g) : "memory");
}

__device__ __forceinline__ void split_store(__nv_bfloat16* H, __nv_bfloat16* L,
                                            size_t e, float4 v) {
    float a0 = v.x, a1 = v.y, a2 = v.z, a3 = v.w;
    __nv_bfloat16 h0 = __float2bfloat16(a0), h1 = __float2bfloat16(a1);
    __nv_bfloat16 h2 = __float2bfloat16(a2), h3 = __float2bfloat16(a3);
    __nv_bfloat16 l0 = __float2bfloat16(a0 - __bfloat162float(h0));
    __nv_bfloat16 l1 = __float2bfloat16(a1 - __bfloat162float(h1));
    __nv_bfloat16 l2 = __float2bfloat16(a2 - __bfloat162float(h2));
    __nv_bfloat16 l3 = __float2bfloat16(a3 - __bfloat162float(h3));
    *(__nv_bfloat162*)&H[e]     = __nv_bfloat162(h0, h1);
    *(__nv_bfloat162*)&H[e + 2] = __nv_bfloat162(h2, h3);
    *(__nv_bfloat162*)&L[e]     = __nv_bfloat162(l0, l1);
    *(__nv_bfloat162*)&L[e + 2] = __nv_bfloat162(l2, l3);
}

// ---------------------------------------------------------------------------
// Launch 1. Elementwise bf16 hi/lo splits: x, W(qkv concat), exp(pos).
// 140 blocks (single wave), 4 independent float4s per thread (MLP=4).
// 140*256*4 = 143360 slots exactly.
// ---------------------------------------------------------------------------
__global__ __launch_bounds__(256)
void split_inputs(const float* __restrict__ x,
                  const float* __restrict__ Wq, const float* __restrict__ Wk,
                  const float* __restrict__ Wv, const float* __restrict__ pos)
{
    const int base = blockIdx.x * 256 + threadIdx.x;
    #pragma unroll
    for (int it = 0; it < 4; it++) {
        int idx = base + it * 35840;
        if (idx < 65536) {                      // x
            float4 v = ((const float4*)x)[idx];
            split_store(g_xh, g_xl, (size_t)idx * 4, v);
        } else if (idx < 131072) {              // exp(pos)
            int i = idx - 65536;
            float4 p = ((const float4*)pos)[i];
            float4 e;
            e.x = __expf(p.x); e.y = __expf(p.y);
            e.z = __expf(p.z); e.w = __expf(p.w);
            split_store(g_Ph, g_Pl, (size_t)i * 4, e);
        } else if (idx < 143360) {              // W concat
            int i = idx - 131072;
            int e = i * 4;
            int mat = e >> 14;
            int off = e & 16383;
            const float* W = (mat == 0) ? Wq : (mat == 1) ? Wk : Wv;
            float4 v = *(const float4*)&W[off];
            split_store(g_Wh, g_Wl, (size_t)e, v);
        }
    }
}

// ---------------------------------------------------------------------------
// Launch 2. Projection GEMM on tensor cores (round-9 proven).
// CTA: 64m x 96n (matched q/k/v d-slice). Epilogue emits g_q AND the
// transposed bf16-split Zt tiles directly.
// ---------------------------------------------------------------------------
__global__ __launch_bounds__(256, 1)
void proj_mma(const float* __restrict__ bq, const float* __restrict__ bk,
              const float* __restrict__ bv)
{
    __shared__ __align__(128) char arena[40960];

    const int tid = threadIdx.x;
    const int wid = tid >> 5, lane = tid & 31;
    const int mw  = wid >> 2, nw = wid & 3;
    const int d0  = blockIdx.x * 32;
    const int m0  = blockIdx.y * 64;

    const uint32_t sm0 = smem_u32(arena);
    const uint32_t sm1 = sm0 + 20480;

    const int am  = (lane & 7) + ((lane >> 3) & 1) * 8;
    const int akb = (lane >> 4) * 8;
    const int bn  = (lane & 7) + ((lane >> 4) & 1) * 8;
    const int bkb = ((lane >> 3) & 1) * 8;

    float c[2][3][4] = {};

    auto load_stage = [&](int s) {
        const uint32_t sb = (s & 1) ? sm1 : sm0;
        const int k0 = s * 32;
        #pragma unroll
        for (int i = 0; i < 5; i++) {
            int cch = tid + i * 256;
            const __nv_bfloat16* src;
            uint32_t so; size_t go;
            if (cch < 512) {
                int hl = cch >> 8, cc = cch & 255;
                int row = cc >> 2, c16 = cc & 3;
                so = sb + hl * 4096 + SWZ64(row * 64 + c16 * 16);
                src = hl ? g_xl : g_xh;
                go = (size_t)(m0 + row) * 128 + k0 + c16 * 8;
            } else {
                int v2 = cch - 512;
                int hl = v2 >= 384, cc = hl ? v2 - 384 : v2;
                int row = cc >> 2, c16 = cc & 3;
                so = sb + 8192 + hl * 6144 + SWZ64(row * 64 + c16 * 16);
                src = hl ? g_Wl : g_Wh;
                go = (size_t)((row >> 5) * 128 + d0 + (row & 31)) * 128 + k0 + c16 * 8;
            }
            cpa16(so, src + go);
        }
        asm volatile("cp.async.commit_group;" ::: "memory");
    };

    load_stage(0);

    for (int s = 0; s < 4; s++) {
        asm volatile("cp.async.wait_group 0;" ::: "memory");
        __syncthreads();
        if (s < 3) load_stage(s + 1);
        const uint32_t sb = (s & 1) ? sm1 : sm0;
        #pragma unroll
        for (int kk = 0; kk < 2; kk++) {
            uint32_t ah[2][4], al[2][4], bh[6], bl[6];
            #pragma unroll
            for (int ms = 0; ms < 2; ms++) {
                int rowA = mw * 32 + ms * 16 + am;
                uint32_t off = SWZ64(rowA * 64 + kk * 32 + akb * 2);
                ldsm4(ah[ms], sb + off);
                ldsm4(al[ms], sb + 4096 + off);
            }
            {
                int rowB = nw * 24 + bn;
                uint32_t off4 = SWZ64(rowB * 64 + kk * 32 + bkb * 2);
                ldsm4(bh, sb + 8192 + off4);
                ldsm4(bl, sb + 14336 + off4);
                int rowB2 = nw * 24 + 16 + (lane & 7);
                uint32_t off2 = SWZ64(rowB2 * 64 + kk * 32 + ((lane >> 3) & 1) * 16);
                ldsm2(bh + 4, sb + 8192 + off2);
                ldsm2(bl + 4, sb + 14336 + off2);
            }
            #pragma unroll
            for (int ms = 0; ms < 2; ms++)
                #pragma unroll
                for (int nf = 0; nf < 3; nf++) {
                    mma16816(c[ms][nf], ah[ms], bh + 2 * nf);
                    mma16816(c[ms][nf], ah[ms], bl + 2 * nf);
                    mma16816(c[ms][nf], al[ms], bh + 2 * nf);
                }
        }
        __syncthreads();
    }

    // ---- epilogue: E/V exchange in arena, then transposed split write ----
    float (*Ebuf)[33] = (float(*)[33])arena;
    float (*Vbuf)[33] = (float(*)[33])(arena + 8448);

    #pragma unroll
    for (int ms = 0; ms < 2; ms++)
        #pragma unroll
        for (int nf = 0; nf < 3; nf++) {
            int ncl = nw * 24 + nf * 8;
            int region = ncl >> 5;
            int dcol = (ncl & 31) + 2 * (lane & 3);
            int r0 = mw * 32 + ms * 16 + (lane >> 2);
            #pragma unroll
            for (int h = 0; h < 2; h++) {
                int r = r0 + 8 * h;
                float v0 = c[ms][nf][2 * h], v1 = c[ms][nf][2 * h + 1];
                int d = d0 + dcol;
                if (region == 0) {
                    float s0 = 1.0f / (1.0f + __expf(-(v0 + bq[d])));
                    float s1 = 1.0f / (1.0f + __expf(-(v1 + bq[d + 1])));
                    *(float2*)&g_q[(size_t)(m0 + r) * 128 + d] = make_float2(s0, s1);
                } else if (region == 1) {
                    Ebuf[r][dcol]     = __expf(v0 + bk[d]);
                    Ebuf[r][dcol + 1] = __expf(v1 + bk[d + 1]);
                } else {
                    Vbuf[r][dcol]     = v0 + bv[d];
                    Vbuf[r][dcol + 1] = v1 + bv[d + 1];
                }
            }
        }
    __syncthreads();

    {
        const int b  = m0 >> 9;
        const int j0 = m0 & 511;
        const int d  = tid >> 3;
        const int jl = (tid & 7) * 8;
        __nv_bfloat16 nh[8], nl[8], dh[8], dl[8];
        #pragma unroll
        for (int i = 0; i < 8; i++) {
            float e = Ebuf[jl + i][d];
            float v = Vbuf[jl + i][d];
            float nm = e * v;
            nh[i] = __float2bfloat16(nm);
            nl[i] = __float2bfloat16(nm - __bfloat162float(nh[i]));
            dh[i] = __float2bfloat16(e);
            dl[i] = __float2bfloat16(e - __bfloat162float(dh[i]));
        }
        size_t rn = (size_t)(b * ZN + d0 + d) * SEQ + j0 + jl;
        size_t rd = (size_t)(b * ZN + 128 + d0 + d) * SEQ + j0 + jl;
        *(uint4*)&g_Zth[rn] = *(const uint4*)nh;
        *(uint4*)&g_Ztl[rn] = *(const uint4*)nl;
        *(uint4*)&g_Zth[rd] = *(const uint4*)dh;
        *(uint4*)&g_Ztl[rd] = *(const uint4*)dl;
    }
}

// ---------------------------------------------------------------------------
// Launch 3. O2 = P @ Z via mma.sync bf16, 3-pass split, ratio fused.
// 512 threads = 2 warpgroups, SPLIT-K: group g covers K in [256g, 256g+256),
// each with a private 3-deep cp.async ring (2 x 48KB dynamic SMEM).
// Group 1 publishes fragments via SMEM; group 0 reduces + fused epilogue.
// Last stage waits with wait_group 0 (fixes round-9 latent race).
// ---------------------------------------------------------------------------
#define AFT_SMEM 98304
__global__ __launch_bounds__(512, 1)
void aft_mma(float* __restrict__ out)
{
    extern __shared__ __align__(128) char arena[];

    const int tid   = threadIdx.x;
    const int group = tid >> 8;
    const int gtid  = tid & 255;
    const int gwid  = gtid >> 5, lane = gtid & 31;
    const int mw    = gwid >> 2, nw = gwid & 3;

    const int d0 = blockIdx.x * 32;
    const int m0 = blockIdx.y * 64;
    const int b  = blockIdx.z;

    const uint32_t gbase = smem_u32(arena) + (uint32_t)group * 49152;

    const int am  = (lane & 7) + ((lane >> 3) & 1) * 8;
    const int akb = (lane >> 4) * 8;
    const int bn  = (lane & 7) + ((lane >> 4) & 1) * 8;
    const int bkb = ((lane >> 3) & 1) * 8;

    float c[2][2][4] = {};

    auto load_stage = [&](int s) {
        const uint32_t sb = gbase + (uint32_t)(s % 3) * 16384;
        const int k0 = group * 256 + s * 32;
        #pragma unroll
        for (int i = 0; i < 4; i++) {
            int cch  = gtid + i * 256;
            int tile = cch >> 8;
            int cc   = cch & 255;
            int row  = cc >> 2, c16 = cc & 3;
            uint32_t so = sb + tile * 4096 + SWZ64(row * 64 + c16 * 16);
            const __nv_bfloat16* src;
            int grow;
            if (tile < 2) {
                grow = m0 + row;
                src = (tile == 0) ? g_Ph : g_Pl;
            } else {
                int rowZ = (row < 32) ? d0 + row : 96 + d0 + row;
                grow = b * ZN + rowZ;
                src = (tile == 2) ? g_Zth : g_Ztl;
            }
            cpa16(so, src + (size_t)grow * SEQ + k0 + c16 * 8);
        }
        asm volatile("cp.async.commit_group;" ::: "memory");
    };

    load_stage(0);
    load_stage(1);

    for (int s = 0; s < 8; s++) {
        if (s == 7) asm volatile("cp.async.wait_group 0;" ::: "memory");
        else        asm volatile("cp.async.wait_group 1;" ::: "memory");
        __syncthreads();
        if (s < 6) load_stage(s + 2);
        const uint32_t sb = gbase + (uint32_t)(s % 3) * 16384;
        #pragma unroll
        for (int kk = 0; kk < 2; kk++) {
            uint32_t ah[2][4], al[2][4], bh[4], bl[4];
            #pragma unroll
            for (int ms = 0; ms < 2; ms++) {
                int rowA = mw * 32 + ms * 16 + am;
                uint32_t off = SWZ64(rowA * 64 + kk * 32 + akb * 2);
                ldsm4(ah[ms], sb + off);
                ldsm4(al[ms], sb + 4096 + off);
            }
            {
                int rowB = nw * 16 + bn;
                uint32_t off = SWZ64(rowB * 64 + kk * 32 + bkb * 2);
                ldsm4(bh, sb + 8192 + off);
                ldsm4(bl, sb + 12288 + off);
            }
            #pragma unroll
            for (int ms = 0; ms < 2; ms++)
                #pragma unroll
                for (int ns = 0; ns < 2; ns++) {
                    mma16816(c[ms][ns], ah[ms], bh + 2 * ns);
                    mma16816(c[ms][ns], ah[ms], bl + 2 * ns);
                    mma16816(c[ms][ns], al[ms], bh + 2 * ns);
                }
        }
    }
    __syncthreads();

    // ---- split-K reduction: group 1 publishes into its (now free) ring ----
    float (*Cred)[66] = (float(*)[66])(arena + 49152);
    float (*den)[34]  = (float(*)[34])(arena + 49152 + 17408);

    if (group == 1) {
        #pragma unroll
        for (int ms = 0; ms < 2; ms++)
            #pragma unroll
            for (int ns = 0; ns < 2; ns++) {
                int dr = nw * 16 + ns * 8 + 2 * (lane & 3);
                int r  = mw * 32 + ms * 16 + (lane >> 2);
                *(float2*)&Cred[r][dr]     = make_float2(c[ms][ns][0], c[ms][ns][1]);
                *(float2*)&Cred[r + 8][dr] = make_float2(c[ms][ns][2], c[ms][ns][3]);
            }
    }
    __syncthreads();
    if (group == 0) {
        #pragma unroll
        for (int ms = 0; ms < 2; ms++)
            #pragma unroll
            for (int ns = 0; ns < 2; ns++) {
                int dr = nw * 16 + ns * 8 + 2 * (lane & 3);
                int r  = mw * 32 + ms * 16 + (lane >> 2);
                float2 p0 = *(const float2*)&Cred[r][dr];
                float2 p1 = *(const float2*)&Cred[r + 8][dr];
                c[ms][ns][0] += p0.x; c[ms][ns][1] += p0.y;
                c[ms][ns][2] += p1.x; c[ms][ns][3] += p1.y;
            }
        // den publication (warps nw>=2 hold den columns)
        if (nw >= 2) {
            #pragma unroll
            for (int ms = 0; ms < 2; ms++)
                #pragma unroll
                for (int ns = 0; ns < 2; ns++) {
                    int dr = (nw - 2) * 16 + ns * 8 + 2 * (lane & 3);
                    int r  = mw * 32 + ms * 16 + (lane >> 2);
                    *(float2*)&den[r][dr]     = make_float2(c[ms][ns][0], c[ms][ns][1]);
                    *(float2*)&den[r + 8][dr] = make_float2(c[ms][ns][2], c[ms][ns][3]);
                }
        }
    }
    __syncthreads();
    if (group == 0 && nw < 2) {
        #pragma unroll
        for (int ms = 0; ms < 2; ms++)
            #pragma unroll
            for (int ns = 0; ns < 2; ns++) {
                int dr = nw * 16 + ns * 8 + 2 * (lane & 3);
                int r  = mw * 32 + ms * 16 + (lane >> 2);
                #pragma unroll
                for (int h = 0; h < 2; h++) {
                    int rr   = r + h * 8;
                    int grow = b * SEQ + m0 + rr;
                    float2 dn = *(float2*)&den[rr][dr];
                    float2 q  = *(const float2*)&g_q[(size_t)grow * DIM + d0 + dr];
                    float2 o;
                    o.x = q.x * c[ms][ns][2 * h]     / dn.x;
                    o.y = q.y * c[ms][ns][2 * h + 1] / dn.y;
                    *(float2*)&out[(size_t)grow * DIM + d0 + dr] = o;
                }
            }
    }
}

// ---------------------------------------------------------------------------
extern "C" void kernel_launch(void* const* d_in, const int* in_sizes, int n_in,
                              void* d_out, int out_size)
{
    const float* x   = (const float*)d_in[0];
    const float* Wq  = (const float*)d_in[1];
    const float* bq  = (const float*)d_in[2];
    const float* Wk  = (const float*)d_in[3];
    const float* bk  = (const float*)d_in[4];
    const float* Wv  = (const float*)d_in[5];
    const float* bv  = (const float*)d_in[6];
    const float* pos = (const float*)d_in[7];
    float* out = (float*)d_out;

    static int attr_done = 0;
    if (!attr_done) {
        cudaFuncSetAttribute(aft_mma, cudaFuncAttributeMaxDynamicSharedMemorySize,
                             AFT_SMEM);
        attr_done = 1;
    }

    split_inputs<<<140, 256>>>(x, Wq, Wk, Wv, pos);
    proj_mma<<<dim3(4, 32), 256>>>(bq, bk, bv);
    aft_mma<<<dim3(4, 8, 4), 512, AFT_SMEM>>>(out);
}